// round 14
// baseline (speedup 1.0000x reference)
#include <cuda_runtime.h>

// LIF neuron Euler step (TemporalReceptiveField), pure elementwise, HBM-bound.
// R13: relative L2 eviction priority (no carveout needed). i0 (67 MB) is
// loaded with DEFAULT (evict-normal) policy; x, v0 and all stores stay .cs
// (evict-first). Across identical graph replays, i0's normal-priority lines
// should survive in the 126 MB L2 while the 335 MB/iter of evict-first
// traffic recycles its own ways -> steady-state i0 reads hit L2, cutting
// DRAM traffic ~17%. Base config = R3: 2x float4/thread, 256 thr, 8192 blocks.

#define DT           0.001f
#define TAU_SYN_INV  200.0f
#define V_TH         1.0f

static constexpr int N_ELEMS = 16 * 64 * 128 * 128;   // 16,777,216
static constexpr int N4      = N_ELEMS / 4;           // 4,194,304 float4s
static constexpr int THREADS = 256;
static constexpr int PER_BLK = THREADS * 2;           // 512 float4s per block
static constexpr int BLOCKS  = N4 / PER_BLK;          // 8192, exact cover

__device__ __forceinline__ void lif4(const float4 xv, const float4 vv, const float4 iv,
                                     const float dt_tau, const float syn_k,
                                     float4& zr, float4& vr, float4& ir)
{
    {
        float vd = fmaf(dt_tau, iv.x - vv.x, vv.x);
        float z  = (vd - V_TH > 0.0f) ? 1.0f : 0.0f;
        zr.x = z;  vr.x = (z > 0.0f) ? 0.0f : vd;
        ir.x = (iv.x - syn_k * iv.x) + xv.x;
    }
    {
        float vd = fmaf(dt_tau, iv.y - vv.y, vv.y);
        float z  = (vd - V_TH > 0.0f) ? 1.0f : 0.0f;
        zr.y = z;  vr.y = (z > 0.0f) ? 0.0f : vd;
        ir.y = (iv.y - syn_k * iv.y) + xv.y;
    }
    {
        float vd = fmaf(dt_tau, iv.z - vv.z, vv.z);
        float z  = (vd - V_TH > 0.0f) ? 1.0f : 0.0f;
        zr.z = z;  vr.z = (z > 0.0f) ? 0.0f : vd;
        ir.z = (iv.z - syn_k * iv.z) + xv.z;
    }
    {
        float vd = fmaf(dt_tau, iv.w - vv.w, vv.w);
        float z  = (vd - V_TH > 0.0f) ? 1.0f : 0.0f;
        zr.w = z;  vr.w = (z > 0.0f) ? 0.0f : vd;
        ir.w = (iv.w - syn_k * iv.w) + xv.w;
    }
}

__global__ __launch_bounds__(THREADS)
void lif_step_kernel(const float4* __restrict__ x,
                     const float4* __restrict__ v0,
                     const float4* __restrict__ i0,
                     const float*  __restrict__ ps,
                     float4* __restrict__ z_out,
                     float4* __restrict__ v_out,
                     float4* __restrict__ i_out)
{
    const int i0idx = blockIdx.x * PER_BLK + threadIdx.x;  // exact cover
    const int i1idx = i0idx + THREADS;

    // x, v0: streamed evict-first (.cs). i0: DEFAULT policy (evict-normal) so
    // its lines outlive the streaming traffic in L2 across graph replays.
    const float4 xv0 = __ldcs(x  + i0idx);
    const float4 vv0 = __ldcs(v0 + i0idx);
    const float4 iv0 = __ldg (i0 + i0idx);
    const float4 xv1 = __ldcs(x  + i1idx);
    const float4 vv1 = __ldcs(v0 + i1idx);
    const float4 iv1 = __ldg (i0 + i1idx);

    // channel = (element_index / (H*W)) % C  ->  (float4_index >> 12) & 63
    const float syn_k   = DT * TAU_SYN_INV;  // 0.2f, matching ref op order
    const float dt_tau0 = DT * __ldg(ps + ((i0idx >> 12) & 63));
    const float dt_tau1 = DT * __ldg(ps + ((i1idx >> 12) & 63));

    float4 zr0, vr0, ir0, zr1, vr1, ir1;
    lif4(xv0, vv0, iv0, dt_tau0, syn_k, zr0, vr0, ir0);
    lif4(xv1, vv1, iv1, dt_tau1, syn_k, zr1, vr1, ir1);

    __stcs(z_out + i0idx, zr0);
    __stcs(v_out + i0idx, vr0);
    __stcs(i_out + i0idx, ir0);
    __stcs(z_out + i1idx, zr1);
    __stcs(v_out + i1idx, vr1);
    __stcs(i_out + i1idx, ir1);
}

extern "C" void kernel_launch(void* const* d_in, const int* in_sizes, int n_in,
                              void* d_out, int out_size)
{
    const float4* x  = (const float4*)d_in[0];
    const float4* v0 = (const float4*)d_in[1];
    const float4* i0 = (const float4*)d_in[2];
    const float*  ps = (const float*)d_in[3];

    float* out = (float*)d_out;
    float4* z_out = (float4*)(out);
    float4* v_out = (float4*)(out + N_ELEMS);
    float4* i_out = (float4*)(out + 2 * N_ELEMS);

    lif_step_kernel<<<BLOCKS, THREADS>>>(x, v0, i0, ps, z_out, v_out, i_out);
}

// round 15
// speedup vs baseline: 1.0387x; 1.0387x over previous
#include <cuda_runtime.h>

// LIF neuron Euler step (TemporalReceptiveField), pure elementwise, HBM-bound.
// FINAL (R14 = R5 config, the wall-time record holder at 62.9us):
// Roofline confirmed across 8 configs: 56.3-58.8us kernel, 74-78% DRAM,
// ~6.1 TB/s = mixed 50/50 R/W HBM turnaround ceiling. Traffic irreducible
// (~400 MB/iter); L2 cross-replay retention unavailable (carveout forbidden,
// priority hints no-op). UNROLL=3: 9 front-batched LDG.128, .cs streaming,
// 48 regs, ~51% occ, 256 thr x 5462 blocks.

#define DT           0.001f
#define TAU_SYN_INV  200.0f
#define V_TH         1.0f

static constexpr int N_ELEMS = 16 * 64 * 128 * 128;   // 16,777,216
static constexpr int N4      = N_ELEMS / 4;           // 4,194,304 float4s (2^22)
static constexpr int THREADS = 256;
static constexpr int UNROLL  = 3;
static constexpr int PER_BLK = THREADS * UNROLL;      // 768 float4s per block
static constexpr int BLOCKS  = (N4 + PER_BLK - 1) / PER_BLK;  // 5462 (last block partial)

__device__ __forceinline__ void lif4(const float4 xv, const float4 vv, const float4 iv,
                                     const float dt_tau, const float syn_k,
                                     float4& zr, float4& vr, float4& ir)
{
    {
        float vd = fmaf(dt_tau, iv.x - vv.x, vv.x);
        float z  = (vd - V_TH > 0.0f) ? 1.0f : 0.0f;
        zr.x = z;  vr.x = (z > 0.0f) ? 0.0f : vd;
        ir.x = (iv.x - syn_k * iv.x) + xv.x;
    }
    {
        float vd = fmaf(dt_tau, iv.y - vv.y, vv.y);
        float z  = (vd - V_TH > 0.0f) ? 1.0f : 0.0f;
        zr.y = z;  vr.y = (z > 0.0f) ? 0.0f : vd;
        ir.y = (iv.y - syn_k * iv.y) + xv.y;
    }
    {
        float vd = fmaf(dt_tau, iv.z - vv.z, vv.z);
        float z  = (vd - V_TH > 0.0f) ? 1.0f : 0.0f;
        zr.z = z;  vr.z = (z > 0.0f) ? 0.0f : vd;
        ir.z = (iv.z - syn_k * iv.z) + xv.z;
    }
    {
        float vd = fmaf(dt_tau, iv.w - vv.w, vv.w);
        float z  = (vd - V_TH > 0.0f) ? 1.0f : 0.0f;
        zr.w = z;  vr.w = (z > 0.0f) ? 0.0f : vd;
        ir.w = (iv.w - syn_k * iv.w) + xv.w;
    }
}

__global__ __launch_bounds__(THREADS)
void lif_step_kernel(const float4* __restrict__ x,
                     const float4* __restrict__ v0,
                     const float4* __restrict__ i0,
                     const float*  __restrict__ ps,
                     float4* __restrict__ z_out,
                     float4* __restrict__ v_out,
                     float4* __restrict__ i_out)
{
    const int base = blockIdx.x * PER_BLK + threadIdx.x;

    int  idx[UNROLL];
    bool ok[UNROLL];
    #pragma unroll
    for (int k = 0; k < UNROLL; k++) {
        idx[k] = base + k * THREADS;
        ok[k]  = idx[k] < N4;
    }

    // Front-batch all loads (streaming: no reuse, evict-first).
    float4 xv[UNROLL], vv[UNROLL], iv[UNROLL];
    #pragma unroll
    for (int k = 0; k < UNROLL; k++) if (ok[k]) xv[k] = __ldcs(x  + idx[k]);
    #pragma unroll
    for (int k = 0; k < UNROLL; k++) if (ok[k]) vv[k] = __ldcs(v0 + idx[k]);
    #pragma unroll
    for (int k = 0; k < UNROLL; k++) if (ok[k]) iv[k] = __ldcs(i0 + idx[k]);

    const float syn_k = DT * TAU_SYN_INV;  // 0.2f, matching ref op order

    #pragma unroll
    for (int k = 0; k < UNROLL; k++) {
        if (!ok[k]) continue;
        // channel = (element_index / (H*W)) % C  ->  (float4_index >> 12) & 63
        const float dt_tau = DT * __ldg(ps + ((idx[k] >> 12) & 63));
        float4 zr, vr, ir;
        lif4(xv[k], vv[k], iv[k], dt_tau, syn_k, zr, vr, ir);
        __stcs(z_out + idx[k], zr);
        __stcs(v_out + idx[k], vr);
        __stcs(i_out + idx[k], ir);
    }
}

extern "C" void kernel_launch(void* const* d_in, const int* in_sizes, int n_in,
                              void* d_out, int out_size)
{
    const float4* x  = (const float4*)d_in[0];
    const float4* v0 = (const float4*)d_in[1];
    const float4* i0 = (const float4*)d_in[2];
    const float*  ps = (const float*)d_in[3];

    float* out = (float*)d_out;
    float4* z_out = (float4*)(out);
    float4* v_out = (float4*)(out + N_ELEMS);
    float4* i_out = (float4*)(out + 2 * N_ELEMS);

    lif_step_kernel<<<BLOCKS, THREADS>>>(x, v0, i0, ps, z_out, v_out, i_out);
}

// round 16
// speedup vs baseline: 1.0393x; 1.0005x over previous
#include <cuda_runtime.h>

// LIF neuron Euler step (TemporalReceptiveField), pure elementwise, HBM-bound.
// FINAL CONFIG (record holder, 2 runs: kernel 56.7/55.2us, wall 62.9/62.0us,
// DRAM up to 79.4% = 6289 GB/s ~= the ~6.3 TB/s LTS/HBM path ceiling).
// UNROLL=3: 9 front-batched LDG.128, .cs streaming loads+stores, 48 regs,
// ~51% occ, 256 thr x 5462 blocks. Resubmitted unmodified — design space
// exhausted (8 configs on one plateau; L2 retention structurally unavailable).

#define DT           0.001f
#define TAU_SYN_INV  200.0f
#define V_TH         1.0f

static constexpr int N_ELEMS = 16 * 64 * 128 * 128;   // 16,777,216
static constexpr int N4      = N_ELEMS / 4;           // 4,194,304 float4s (2^22)
static constexpr int THREADS = 256;
static constexpr int UNROLL  = 3;
static constexpr int PER_BLK = THREADS * UNROLL;      // 768 float4s per block
static constexpr int BLOCKS  = (N4 + PER_BLK - 1) / PER_BLK;  // 5462 (last block partial)

__device__ __forceinline__ void lif4(const float4 xv, const float4 vv, const float4 iv,
                                     const float dt_tau, const float syn_k,
                                     float4& zr, float4& vr, float4& ir)
{
    {
        float vd = fmaf(dt_tau, iv.x - vv.x, vv.x);
        float z  = (vd - V_TH > 0.0f) ? 1.0f : 0.0f;
        zr.x = z;  vr.x = (z > 0.0f) ? 0.0f : vd;
        ir.x = (iv.x - syn_k * iv.x) + xv.x;
    }
    {
        float vd = fmaf(dt_tau, iv.y - vv.y, vv.y);
        float z  = (vd - V_TH > 0.0f) ? 1.0f : 0.0f;
        zr.y = z;  vr.y = (z > 0.0f) ? 0.0f : vd;
        ir.y = (iv.y - syn_k * iv.y) + xv.y;
    }
    {
        float vd = fmaf(dt_tau, iv.z - vv.z, vv.z);
        float z  = (vd - V_TH > 0.0f) ? 1.0f : 0.0f;
        zr.z = z;  vr.z = (z > 0.0f) ? 0.0f : vd;
        ir.z = (iv.z - syn_k * iv.z) + xv.z;
    }
    {
        float vd = fmaf(dt_tau, iv.w - vv.w, vv.w);
        float z  = (vd - V_TH > 0.0f) ? 1.0f : 0.0f;
        zr.w = z;  vr.w = (z > 0.0f) ? 0.0f : vd;
        ir.w = (iv.w - syn_k * iv.w) + xv.w;
    }
}

__global__ __launch_bounds__(THREADS)
void lif_step_kernel(const float4* __restrict__ x,
                     const float4* __restrict__ v0,
                     const float4* __restrict__ i0,
                     const float*  __restrict__ ps,
                     float4* __restrict__ z_out,
                     float4* __restrict__ v_out,
                     float4* __restrict__ i_out)
{
    const int base = blockIdx.x * PER_BLK + threadIdx.x;

    int  idx[UNROLL];
    bool ok[UNROLL];
    #pragma unroll
    for (int k = 0; k < UNROLL; k++) {
        idx[k] = base + k * THREADS;
        ok[k]  = idx[k] < N4;
    }

    // Front-batch all loads (streaming: no reuse, evict-first).
    float4 xv[UNROLL], vv[UNROLL], iv[UNROLL];
    #pragma unroll
    for (int k = 0; k < UNROLL; k++) if (ok[k]) xv[k] = __ldcs(x  + idx[k]);
    #pragma unroll
    for (int k = 0; k < UNROLL; k++) if (ok[k]) vv[k] = __ldcs(v0 + idx[k]);
    #pragma unroll
    for (int k = 0; k < UNROLL; k++) if (ok[k]) iv[k] = __ldcs(i0 + idx[k]);

    const float syn_k = DT * TAU_SYN_INV;  // 0.2f, matching ref op order

    #pragma unroll
    for (int k = 0; k < UNROLL; k++) {
        if (!ok[k]) continue;
        // channel = (element_index / (H*W)) % C  ->  (float4_index >> 12) & 63
        const float dt_tau = DT * __ldg(ps + ((idx[k] >> 12) & 63));
        float4 zr, vr, ir;
        lif4(xv[k], vv[k], iv[k], dt_tau, syn_k, zr, vr, ir);
        __stcs(z_out + idx[k], zr);
        __stcs(v_out + idx[k], vr);
        __stcs(i_out + idx[k], ir);
    }
}

extern "C" void kernel_launch(void* const* d_in, const int* in_sizes, int n_in,
                              void* d_out, int out_size)
{
    const float4* x  = (const float4*)d_in[0];
    const float4* v0 = (const float4*)d_in[1];
    const float4* i0 = (const float4*)d_in[2];
    const float*  ps = (const float*)d_in[3];

    float* out = (float*)d_out;
    float4* z_out = (float4*)(out);
    float4* v_out = (float4*)(out + N_ELEMS);
    float4* i_out = (float4*)(out + 2 * N_ELEMS);

    lif_step_kernel<<<BLOCKS, THREADS>>>(x, v0, i0, ps, z_out, v_out, i_out);
}

// round 17
// speedup vs baseline: 1.0398x; 1.0005x over previous
#include <cuda_runtime.h>

// LIF neuron Euler step (TemporalReceptiveField), pure elementwise, HBM-bound.
// FINAL CONFIG — 3 runs: kernel 56.7/55.2/56.3us, wall 62.9/62.0/61.95us,
// DRAM 77-79% (6.2-6.3 TB/s ~= B300's ~6300 B/cyc LTS/HBM path ceiling).
// UNROLL=3: 9 front-batched LDG.128, .cs streaming loads+stores, 48 regs,
// ~51% occ, 256 thr x 5462 blocks. Design space exhausted:
//  - traffic irreducible (~400 MB/iter nominal, ~350 MB effective)
//  - occ x MLP swept {81%x6, 51%x9, 40%x12, 77%x3(v8)} -> plateau
//  - L2 cross-replay retention structurally unavailable (carveout forbidden,
//    eviction-priority hints no-op on this part)
// Submitted byte-identical; further changes are noise, not optimization.

#define DT           0.001f
#define TAU_SYN_INV  200.0f
#define V_TH         1.0f

static constexpr int N_ELEMS = 16 * 64 * 128 * 128;   // 16,777,216
static constexpr int N4      = N_ELEMS / 4;           // 4,194,304 float4s (2^22)
static constexpr int THREADS = 256;
static constexpr int UNROLL  = 3;
static constexpr int PER_BLK = THREADS * UNROLL;      // 768 float4s per block
static constexpr int BLOCKS  = (N4 + PER_BLK - 1) / PER_BLK;  // 5462 (last block partial)

__device__ __forceinline__ void lif4(const float4 xv, const float4 vv, const float4 iv,
                                     const float dt_tau, const float syn_k,
                                     float4& zr, float4& vr, float4& ir)
{
    {
        float vd = fmaf(dt_tau, iv.x - vv.x, vv.x);
        float z  = (vd - V_TH > 0.0f) ? 1.0f : 0.0f;
        zr.x = z;  vr.x = (z > 0.0f) ? 0.0f : vd;
        ir.x = (iv.x - syn_k * iv.x) + xv.x;
    }
    {
        float vd = fmaf(dt_tau, iv.y - vv.y, vv.y);
        float z  = (vd - V_TH > 0.0f) ? 1.0f : 0.0f;
        zr.y = z;  vr.y = (z > 0.0f) ? 0.0f : vd;
        ir.y = (iv.y - syn_k * iv.y) + xv.y;
    }
    {
        float vd = fmaf(dt_tau, iv.z - vv.z, vv.z);
        float z  = (vd - V_TH > 0.0f) ? 1.0f : 0.0f;
        zr.z = z;  vr.z = (z > 0.0f) ? 0.0f : vd;
        ir.z = (iv.z - syn_k * iv.z) + xv.z;
    }
    {
        float vd = fmaf(dt_tau, iv.w - vv.w, vv.w);
        float z  = (vd - V_TH > 0.0f) ? 1.0f : 0.0f;
        zr.w = z;  vr.w = (z > 0.0f) ? 0.0f : vd;
        ir.w = (iv.w - syn_k * iv.w) + xv.w;
    }
}

__global__ __launch_bounds__(THREADS)
void lif_step_kernel(const float4* __restrict__ x,
                     const float4* __restrict__ v0,
                     const float4* __restrict__ i0,
                     const float*  __restrict__ ps,
                     float4* __restrict__ z_out,
                     float4* __restrict__ v_out,
                     float4* __restrict__ i_out)
{
    const int base = blockIdx.x * PER_BLK + threadIdx.x;

    int  idx[UNROLL];
    bool ok[UNROLL];
    #pragma unroll
    for (int k = 0; k < UNROLL; k++) {
        idx[k] = base + k * THREADS;
        ok[k]  = idx[k] < N4;
    }

    // Front-batch all loads (streaming: no reuse, evict-first).
    float4 xv[UNROLL], vv[UNROLL], iv[UNROLL];
    #pragma unroll
    for (int k = 0; k < UNROLL; k++) if (ok[k]) xv[k] = __ldcs(x  + idx[k]);
    #pragma unroll
    for (int k = 0; k < UNROLL; k++) if (ok[k]) vv[k] = __ldcs(v0 + idx[k]);
    #pragma unroll
    for (int k = 0; k < UNROLL; k++) if (ok[k]) iv[k] = __ldcs(i0 + idx[k]);

    const float syn_k = DT * TAU_SYN_INV;  // 0.2f, matching ref op order

    #pragma unroll
    for (int k = 0; k < UNROLL; k++) {
        if (!ok[k]) continue;
        // channel = (element_index / (H*W)) % C  ->  (float4_index >> 12) & 63
        const float dt_tau = DT * __ldg(ps + ((idx[k] >> 12) & 63));
        float4 zr, vr, ir;
        lif4(xv[k], vv[k], iv[k], dt_tau, syn_k, zr, vr, ir);
        __stcs(z_out + idx[k], zr);
        __stcs(v_out + idx[k], vr);
        __stcs(i_out + idx[k], ir);
    }
}

extern "C" void kernel_launch(void* const* d_in, const int* in_sizes, int n_in,
                              void* d_out, int out_size)
{
    const float4* x  = (const float4*)d_in[0];
    const float4* v0 = (const float4*)d_in[1];
    const float4* i0 = (const float4*)d_in[2];
    const float*  ps = (const float*)d_in[3];

    float* out = (float*)d_out;
    float4* z_out = (float4*)(out);
    float4* v_out = (float4*)(out + N_ELEMS);
    float4* i_out = (float4*)(out + 2 * N_ELEMS);

    lif_step_kernel<<<BLOCKS, THREADS>>>(x, v0, i0, ps, z_out, v_out, i_out);
}